// round 12
// baseline (speedup 1.0000x reference)
#include <cuda_runtime.h>
#include <cuda_bf16.h>
#include <cstdint>

#define NNODES 100000
#define NEDGES 1600000
#define DHID 128
#define DOUT 64
#define NTILES ((NNODES + 127) / 128)   // 782

// ---------------- device scratch (referenced ONLY from device code) ----------
__device__ __nv_bfloat16 g_h[(size_t)NNODES * DHID];    // GEMM output, bf16
__device__ __nv_bfloat16 g_agg[(size_t)NNODES * DHID];  // gathered aggregate, bf16
__device__ int   g_cnt[NNODES + 1];                     // histogram / cursor
__device__ int   g_off[NNODES + 1];                     // CSR offsets (by dst)
__device__ int2  g_pe[NEDGES + 8];                      // permuted edges {src, w}
__device__ float g_wout[NNODES];                        // per-node outgoing weight
__device__ float g_stats[2 * DHID];
__device__ float g_bnsc[DHID];
__device__ float g_bnsh[DHID];
__device__ float g_s[DHID];
__device__ __nv_bfloat16 g_wt0[DHID * DHID];            // Bt0[n][k] = bf16(W0[k][n])
__device__ __nv_bfloat16 g_wt1[DHID * DHID];            // Bt1[n][k] = bf16(W1[k][n])

// ---------------- init -------------------------------------------------------
__global__ void zero_init_kernel() {
    int i = blockIdx.x * blockDim.x + threadIdx.x;
    int stride = gridDim.x * blockDim.x;
    for (int j = i; j <= NNODES; j += stride) g_cnt[j] = 0;
    for (int j = i; j < NNODES; j += stride) g_wout[j] = 0.f;
    if (i < 2 * DHID) g_stats[i] = 0.f;
    if (i < DHID) g_s[i] = 0.f;
}

// ---------------- CSR build + out-weight histogram ---------------------------
__global__ void hist_kernel(const int* __restrict__ src,
                            const int* __restrict__ dst,
                            const float* __restrict__ ew) {
    int i = blockIdx.x * blockDim.x + threadIdx.x;
    int stride = gridDim.x * blockDim.x;
    for (int e = i; e < NEDGES; e += stride) {
        atomicAdd(&g_cnt[dst[e]], 1);
        atomicAdd(&g_wout[src[e]], ew[e]);
    }
}

__global__ void scan_kernel() {
    __shared__ int sh[1024];
    int t = threadIdx.x;
    const int C = (NNODES + 1023) / 1024;
    int base = t * C;
    int lim = base + C < NNODES ? base + C : NNODES;
    int s = 0;
    for (int i = base; i < lim; i++) s += g_cnt[i];
    sh[t] = s;
    __syncthreads();
    for (int off = 1; off < 1024; off <<= 1) {
        int v = (t >= off) ? sh[t - off] : 0;
        __syncthreads();
        sh[t] += v;
        __syncthreads();
    }
    int run = sh[t] - s;
    for (int i = base; i < lim; i++) {
        int c = g_cnt[i];
        g_off[i] = run;
        g_cnt[i] = run;
        run += c;
    }
    if (t == 1023) g_off[NNODES] = sh[1023];
}

__global__ void permute_kernel(const int* __restrict__ src,
                               const int* __restrict__ dst,
                               const float* __restrict__ ew) {
    int i = blockIdx.x * blockDim.x + threadIdx.x;
    int stride = gridDim.x * blockDim.x;
    for (int e = i; e < NEDGES; e += stride) {
        int d = dst[e];
        int pos = atomicAdd(&g_cnt[d], 1);
        g_pe[pos] = make_int2(src[e], __float_as_int(ew[e]));
    }
}

// ---------------- W prep: Wt[n][k] = bf16(W[k][n]) ---------------------------
__global__ void prep_wt_kernel(const float* __restrict__ W0,
                               const float* __restrict__ W1) {
    int i = blockIdx.x * blockDim.x + threadIdx.x;
    if (i >= 2 * DHID * DHID) return;
    int w = i >> 14;
    int idx = i & 16383;
    int k = idx >> 7, n = idx & 127;
    const float* W = w ? W1 : W0;
    __nv_bfloat16 v = __float2bfloat16(W[k * DHID + n]);
    (w ? g_wt1 : g_wt0)[n * DHID + k] = v;
}

// ---------------- HMMA bf16 GEMM: H = bnrelu?(X) @ W  ------------------------
#define ST 136

__device__ __forceinline__ void mma16816(float* c, uint32_t a0, uint32_t a1,
                                         uint32_t a2, uint32_t a3,
                                         uint32_t b0, uint32_t b1) {
    asm volatile(
        "mma.sync.aligned.m16n8k16.row.col.f32.bf16.bf16.f32 "
        "{%0,%1,%2,%3}, {%4,%5,%6,%7}, {%8,%9}, {%0,%1,%2,%3};"
        : "+f"(c[0]), "+f"(c[1]), "+f"(c[2]), "+f"(c[3])
        : "r"(a0), "r"(a1), "r"(a2), "r"(a3), "r"(b0), "r"(b1));
}

__global__ void __launch_bounds__(256)
gemm_hmma_kernel(const float* __restrict__ Xin, int layer) {
    extern __shared__ __nv_bfloat16 sm[];
    __nv_bfloat16* A_sh = sm;              // [128][ST]
    __nv_bfloat16* B_sh = sm + 128 * ST;   // Bt: [n][k], [128][ST]
    const int tid = threadIdx.x;
    const int row0 = blockIdx.x * 128;

    for (int i = tid; i < 8192; i += 256) {
        int r = i >> 6;
        int c = (i & 63) * 2;
        float2 xv = make_float2(0.f, 0.f);
        int gr = row0 + r;
        if (gr < NNODES) {
            if (layer) {
                uint32_t raw = *(const uint32_t*)(g_agg + (size_t)gr * DHID + c);
                xv = __bfloat1622float2(*(__nv_bfloat162*)&raw);
                float2 sc = *(const float2*)(g_bnsc + c);
                float2 sh = *(const float2*)(g_bnsh + c);
                xv.x = fmaxf(0.f, xv.x * sc.x + sh.x);
                xv.y = fmaxf(0.f, xv.y * sc.y + sh.y);
            } else {
                xv = *(const float2*)(Xin + (size_t)gr * DHID + c);
            }
        }
        __nv_bfloat162 bv = __floats2bfloat162_rn(xv.x, xv.y);
        *(uint32_t*)(A_sh + r * ST + c) = *(uint32_t*)&bv;
    }
    {
        const uint4* srcw = (const uint4*)(layer ? g_wt1 : g_wt0);
        for (int i = tid; i < 2048; i += 256) {
            int n = i >> 4, kq = i & 15;
            *(uint4*)(B_sh + n * ST + kq * 8) = srcw[i];
        }
    }
    __syncthreads();

    const int wid = tid >> 5, lane = tid & 31;
    const int wm = (wid & 3) * 32;
    const int wn = (wid >> 2) * 64;
    const int g = lane >> 2, q = lane & 3;

    float acc[2][8][4];
#pragma unroll
    for (int mt = 0; mt < 2; mt++)
#pragma unroll
        for (int nt = 0; nt < 8; nt++)
#pragma unroll
            for (int j = 0; j < 4; j++) acc[mt][nt][j] = 0.f;

#pragma unroll
    for (int ks = 0; ks < 8; ks++) {
        int k0 = ks * 16;
        uint32_t af[2][4];
#pragma unroll
        for (int mt = 0; mt < 2; mt++) {
            const __nv_bfloat16* ap = A_sh + (wm + mt * 16 + g) * ST + k0 + q * 2;
            af[mt][0] = *(const uint32_t*)(ap);
            af[mt][1] = *(const uint32_t*)(ap + 8 * ST);
            af[mt][2] = *(const uint32_t*)(ap + 8);
            af[mt][3] = *(const uint32_t*)(ap + 8 * ST + 8);
        }
#pragma unroll
        for (int nt = 0; nt < 8; nt++) {
            const __nv_bfloat16* bp = B_sh + (wn + nt * 8 + g) * ST + k0 + q * 2;
            uint32_t b0 = *(const uint32_t*)(bp);
            uint32_t b1 = *(const uint32_t*)(bp + 8);
#pragma unroll
            for (int mt = 0; mt < 2; mt++)
                mma16816(acc[mt][nt], af[mt][0], af[mt][1], af[mt][2], af[mt][3],
                         b0, b1);
        }
    }

#pragma unroll
    for (int mt = 0; mt < 2; mt++) {
        int r0 = row0 + wm + mt * 16 + g;
        int r1 = r0 + 8;
#pragma unroll
        for (int nt = 0; nt < 8; nt++) {
            int col = wn + nt * 8 + q * 2;
            if (r0 < NNODES) {
                __nv_bfloat162 v = __floats2bfloat162_rn(acc[mt][nt][0],
                                                         acc[mt][nt][1]);
                *(uint32_t*)(g_h + (size_t)r0 * DHID + col) = *(uint32_t*)&v;
            }
            if (r1 < NNODES) {
                __nv_bfloat162 v = __floats2bfloat162_rn(acc[mt][nt][2],
                                                         acc[mt][nt][3]);
                *(uint32_t*)(g_h + (size_t)r1 * DHID + col) = *(uint32_t*)&v;
            }
        }
    }
}

// ---------------- gather conv: paired-edge half-warp scheme ------------------
// Lanes 0-15 process edge e, lanes 16-31 edge e+1; each lane loads uint4
// (8 cols). One warp load instruction fetches TWO 256B rows. 8 edges per
// unrolled iter -> 4 independent row loads in flight. Cross-half shfl merge.
__device__ __forceinline__ void accum8(float* acc, uint4 h, float w) {
    float2 f0 = __bfloat1622float2(*(__nv_bfloat162*)&h.x);
    float2 f1 = __bfloat1622float2(*(__nv_bfloat162*)&h.y);
    float2 f2 = __bfloat1622float2(*(__nv_bfloat162*)&h.z);
    float2 f3 = __bfloat1622float2(*(__nv_bfloat162*)&h.w);
    acc[0] += f0.x * w; acc[1] += f0.y * w;
    acc[2] += f1.x * w; acc[3] += f1.y * w;
    acc[4] += f2.x * w; acc[5] += f2.y * w;
    acc[6] += f3.x * w; acc[7] += f3.y * w;
}

__global__ void gather_conv_kernel() {
    const int lane = threadIdx.x & 31;
    const int half = lane >> 4;      // 0 or 1
    const int hl = lane & 15;        // 0..15, covers cols hl*8 .. hl*8+7
    int warp = (blockIdx.x * blockDim.x + threadIdx.x) >> 5;
    int nw = (gridDim.x * blockDim.x) >> 5;

    float s8[8], q8[8];
#pragma unroll
    for (int j = 0; j < 8; j++) { s8[j] = 0.f; q8[j] = 0.f; }

    for (int n = warp; n < NNODES; n += nw) {
        int beg = __ldg(&g_off[n]);
        int end = __ldg(&g_off[n + 1]);
        float acc[8];
#pragma unroll
        for (int j = 0; j < 8; j++) acc[j] = 0.f;

        int e = beg;
        for (; e + 8 <= end; e += 8) {
            int2 pA = __ldg(g_pe + e + half);
            int2 pB = __ldg(g_pe + e + 2 + half);
            int2 pC = __ldg(g_pe + e + 4 + half);
            int2 pD = __ldg(g_pe + e + 6 + half);
            uint4 hA = __ldg((const uint4*)(g_h + (size_t)pA.x * DHID) + hl);
            uint4 hB = __ldg((const uint4*)(g_h + (size_t)pB.x * DHID) + hl);
            uint4 hC = __ldg((const uint4*)(g_h + (size_t)pC.x * DHID) + hl);
            uint4 hD = __ldg((const uint4*)(g_h + (size_t)pD.x * DHID) + hl);
            accum8(acc, hA, __int_as_float(pA.y));
            accum8(acc, hB, __int_as_float(pB.y));
            accum8(acc, hC, __int_as_float(pC.y));
            accum8(acc, hD, __int_as_float(pD.y));
        }
        // remainder: 2 edges per iter with predicated second half
        for (; e < end; e += 2) {
            int ee = e + half;
            int valid = ee < end;
            int2 p = __ldg(g_pe + (valid ? ee : e));
            float w = valid ? __int_as_float(p.y) : 0.f;
            uint4 h = __ldg((const uint4*)(g_h + (size_t)p.x * DHID) + hl);
            accum8(acc, h, w);
        }
        // merge halves
#pragma unroll
        for (int j = 0; j < 8; j++)
            acc[j] += __shfl_xor_sync(0xFFFFFFFFu, acc[j], 16);

        if (half == 0) {
            __nv_bfloat162 c0 = __floats2bfloat162_rn(acc[0], acc[1]);
            __nv_bfloat162 c1 = __floats2bfloat162_rn(acc[2], acc[3]);
            __nv_bfloat162 c2 = __floats2bfloat162_rn(acc[4], acc[5]);
            __nv_bfloat162 c3 = __floats2bfloat162_rn(acc[6], acc[7]);
            uint4 pk = make_uint4(*(uint32_t*)&c0, *(uint32_t*)&c1,
                                  *(uint32_t*)&c2, *(uint32_t*)&c3);
            ((uint4*)(g_agg + (size_t)n * DHID))[hl] = pk;
#pragma unroll
            for (int j = 0; j < 8; j++) {
                s8[j] += acc[j];
                q8[j] += acc[j] * acc[j];
            }
        }
    }

    __shared__ float st[2 * DHID];
    if (threadIdx.x < 2 * DHID) st[threadIdx.x] = 0.f;
    __syncthreads();
    if (half == 0) {
        int c = hl * 8;
#pragma unroll
        for (int j = 0; j < 8; j++) {
            atomicAdd(&st[c + j], s8[j]);
            atomicAdd(&st[DHID + c + j], q8[j]);
        }
    }
    __syncthreads();
    if (threadIdx.x < 2 * DHID) atomicAdd(&g_stats[threadIdx.x], st[threadIdx.x]);
}

// ---------------- BN finalize ------------------------------------------------
__global__ void bn_finalize_kernel(const float* __restrict__ gamma,
                                   const float* __restrict__ beta) {
    int c = threadIdx.x;
    const float invN = 1.0f / (float)NNODES;
    float mu = g_stats[c] * invN;
    float var = g_stats[DHID + c] * invN - mu * mu;
    float sc = gamma[c] * rsqrtf(var + 1e-5f);
    g_bnsc[c] = sc;
    g_bnsh[c] = beta[c] - mu * sc;
    g_stats[c] = 0.f;
    g_stats[DHID + c] = 0.f;
}

// ---------------- final: s = sum_n w_out[n] * relu(bn(agg[n])) ---------------
__global__ void node_reduce_kernel() {
    int c = threadIdx.x;
    float sc = g_bnsc[c], sh = g_bnsh[c];
    float s = 0.f;
    for (int n = blockIdx.x; n < NNODES; n += gridDim.x) {
        float v = __bfloat162float(g_agg[(size_t)n * DHID + c]);
        v = fmaxf(0.f, v * sc + sh);
        s += v * g_wout[n];
    }
    atomicAdd(&g_s[c], s);
}

__global__ void final_kernel(const float* __restrict__ W2,
                             const float* __restrict__ b2,
                             float* __restrict__ out) {
    int j = threadIdx.x;
    if (j < DOUT) {
        float acc = 0.f;
        for (int k = 0; k < DHID; k++) acc += g_s[k] * W2[k * DOUT + j];
        out[j] = acc + (float)NNODES * b2[j];
    }
}

// ----------------------------------------------------------------------------
#define GEMM_SMEM (2 * 128 * ST * 2)   // 69632 bytes

extern "C" void kernel_launch(void* const* d_in, const int* in_sizes, int n_in,
                              void* d_out, int out_size) {
    const float* nf  = (const float*)d_in[0];
    const int*   ei  = (const int*)d_in[1];
    const float* ew  = (const float*)d_in[2];
    const float* W0  = (const float*)d_in[3];
    // b0 (d_in[4]) and b1 (d_in[6]) cancel exactly through BatchNorm
    const float* W1  = (const float*)d_in[5];
    const float* W2  = (const float*)d_in[7];
    const float* b2  = (const float*)d_in[8];
    const float* g0  = (const float*)d_in[9];
    const float* be0 = (const float*)d_in[10];
    const float* g1  = (const float*)d_in[11];
    const float* be1 = (const float*)d_in[12];
    const int* src = ei;
    const int* dst = ei + NEDGES;
    float* out = (float*)d_out;

    static int inited = 0;
    if (!inited) {
        cudaFuncSetAttribute(gemm_hmma_kernel,
                             cudaFuncAttributeMaxDynamicSharedMemorySize,
                             GEMM_SMEM);
        inited = 1;
    }

    // CSR build (by dst) + w_out histogram — single stream, proven ordering
    zero_init_kernel<<<512, 256>>>();
    hist_kernel<<<1024, 256>>>(src, dst, ew);
    scan_kernel<<<1, 1024>>>();
    permute_kernel<<<1024, 256>>>(src, dst, ew);
    prep_wt_kernel<<<128, 256>>>(W0, W1);

    // layer 0
    gemm_hmma_kernel<<<NTILES, 256, GEMM_SMEM>>>(nf, 0);
    gather_conv_kernel<<<1024, 256>>>();
    bn_finalize_kernel<<<1, 128>>>(g0, be0);

    // layer 1 (BN0+ReLU fused into A-staging)
    gemm_hmma_kernel<<<NTILES, 256, GEMM_SMEM>>>(nullptr, 1);
    gather_conv_kernel<<<1024, 256>>>();
    bn_finalize_kernel<<<1, 128>>>(g1, be1);

    // final conv collapsed twice: edge sum == w_out-weighted node sum
    node_reduce_kernel<<<2048, 128>>>();
    final_kernel<<<1, 64>>>(W2, b2, out);
}

// round 13
// speedup vs baseline: 1.4234x; 1.4234x over previous
#include <cuda_runtime.h>
#include <cuda_bf16.h>
#include <cstdint>

#define NNODES 100000
#define NEDGES 1600000
#define DHID 128
#define DOUT 64
#define NTILES ((NNODES + 127) / 128)   // 782
#define SCAN_BLK 1024
#define SCAN_NB ((NNODES + SCAN_BLK - 1) / SCAN_BLK)   // 98

// ---------------- device scratch (referenced ONLY from device code) ----------
__device__ __nv_bfloat16 g_h[(size_t)NNODES * DHID];    // GEMM output, bf16
__device__ __nv_bfloat16 g_agg[(size_t)NNODES * DHID];  // gathered aggregate, bf16
__device__ int   g_cnt[SCAN_NB * SCAN_BLK];             // histogram / cursor (padded)
__device__ int   g_off[NNODES + 1];                     // CSR offsets (by dst)
__device__ int   g_part[SCAN_NB];                       // scan block partials
__device__ int2  g_pe[NEDGES + 4];                      // permuted edges {src, w}
__device__ float g_wout[NNODES];                        // per-node outgoing weight
__device__ float g_stats[2 * DHID];
__device__ float g_bnsc[DHID];
__device__ float g_bnsh[DHID];
__device__ float g_s[DHID];
__device__ __nv_bfloat16 g_wt0[DHID * DHID];            // Bt0[n][k] = bf16(W0[k][n])
__device__ __nv_bfloat16 g_wt1[DHID * DHID];            // Bt1[n][k] = bf16(W1[k][n])

// ---------------- init -------------------------------------------------------
__global__ void zero_init_kernel() {
    int i = blockIdx.x * blockDim.x + threadIdx.x;
    int stride = gridDim.x * blockDim.x;
    for (int j = i; j < SCAN_NB * SCAN_BLK; j += stride) g_cnt[j] = 0;
    for (int j = i; j < NNODES; j += stride) g_wout[j] = 0.f;
    if (i < 2 * DHID) g_stats[i] = 0.f;
    if (i < DHID) g_s[i] = 0.f;
}

// ---------------- CSR build + out-weight histogram ---------------------------
__global__ void hist_kernel(const int* __restrict__ src,
                            const int* __restrict__ dst,
                            const float* __restrict__ ew) {
    int i = blockIdx.x * blockDim.x + threadIdx.x;
    int stride = gridDim.x * blockDim.x;
    for (int e = i; e < NEDGES; e += stride) {
        atomicAdd(&g_cnt[dst[e]], 1);
        atomicAdd(&g_wout[src[e]], ew[e]);
    }
}

// scan phase 1: per-block sums (98 blocks x 256 threads, 4 ints/thread)
__global__ void scan_sums_kernel() {
    __shared__ int sh[256];
    int b = blockIdx.x, t = threadIdx.x;
    const int4* p = (const int4*)(g_cnt + b * SCAN_BLK);
    int4 v = p[t];
    sh[t] = v.x + v.y + v.z + v.w;
    __syncthreads();
    for (int o = 128; o > 0; o >>= 1) {
        if (t < o) sh[t] += sh[t + o];
        __syncthreads();
    }
    if (t == 0) g_part[b] = sh[0];
}

// scan phase 2: exclusive scan of 98 partials (1 block, 128 threads)
__global__ void scan_part_kernel() {
    __shared__ int sh[128];
    int t = threadIdx.x;
    int v = (t < SCAN_NB) ? g_part[t] : 0;
    sh[t] = v;
    __syncthreads();
    for (int o = 1; o < 128; o <<= 1) {
        int x = (t >= o) ? sh[t - o] : 0;
        __syncthreads();
        sh[t] += x;
        __syncthreads();
    }
    if (t < SCAN_NB) g_part[t] = sh[t] - v;   // exclusive block prefix
    if (t == 0) g_off[NNODES] = NEDGES;
}

// scan phase 3: block-local scan + write offsets & cursors
__global__ void scan_write_kernel() {
    __shared__ int sh[256];
    int b = blockIdx.x, t = threadIdx.x;
    int base = b * SCAN_BLK + t * 4;
    int4 v = ((const int4*)(g_cnt + b * SCAN_BLK))[t];
    int s = v.x + v.y + v.z + v.w;
    sh[t] = s;
    __syncthreads();
    for (int o = 1; o < 256; o <<= 1) {
        int x = (t >= o) ? sh[t - o] : 0;
        __syncthreads();
        sh[t] += x;
        __syncthreads();
    }
    int run = g_part[b] + sh[t] - s;   // global exclusive prefix for this thread
    int vv[4] = {v.x, v.y, v.z, v.w};
#pragma unroll
    for (int i = 0; i < 4; i++) {
        int idx = base + i;
        if (idx < NNODES) {
            g_off[idx] = run;
            g_cnt[idx] = run;   // cursor for permute
            run += vv[i];
        }
    }
}

__global__ void permute_kernel(const int* __restrict__ src,
                               const int* __restrict__ dst,
                               const float* __restrict__ ew) {
    int i = blockIdx.x * blockDim.x + threadIdx.x;
    int stride = gridDim.x * blockDim.x;
    for (int e = i; e < NEDGES; e += stride) {
        int d = dst[e];
        int pos = atomicAdd(&g_cnt[d], 1);
        g_pe[pos] = make_int2(src[e], __float_as_int(ew[e]));
    }
}

// ---------------- W prep: Wt[n][k] = bf16(W[k][n]) ---------------------------
__global__ void prep_wt_kernel(const float* __restrict__ W0,
                               const float* __restrict__ W1) {
    int i = blockIdx.x * blockDim.x + threadIdx.x;
    if (i >= 2 * DHID * DHID) return;
    int w = i >> 14;
    int idx = i & 16383;
    int k = idx >> 7, n = idx & 127;
    const float* W = w ? W1 : W0;
    __nv_bfloat16 v = __float2bfloat16(W[k * DHID + n]);
    (w ? g_wt1 : g_wt0)[n * DHID + k] = v;
}

// ---------------- HMMA bf16 GEMM: H = bnrelu?(X) @ W  ------------------------
#define ST 136

__device__ __forceinline__ void mma16816(float* c, uint32_t a0, uint32_t a1,
                                         uint32_t a2, uint32_t a3,
                                         uint32_t b0, uint32_t b1) {
    asm volatile(
        "mma.sync.aligned.m16n8k16.row.col.f32.bf16.bf16.f32 "
        "{%0,%1,%2,%3}, {%4,%5,%6,%7}, {%8,%9}, {%0,%1,%2,%3};"
        : "+f"(c[0]), "+f"(c[1]), "+f"(c[2]), "+f"(c[3])
        : "r"(a0), "r"(a1), "r"(a2), "r"(a3), "r"(b0), "r"(b1));
}

__global__ void __launch_bounds__(256)
gemm_hmma_kernel(const float* __restrict__ Xin, int layer) {
    extern __shared__ __nv_bfloat16 sm[];
    __nv_bfloat16* A_sh = sm;              // [128][ST]
    __nv_bfloat16* B_sh = sm + 128 * ST;   // Bt: [n][k], [128][ST]
    const int tid = threadIdx.x;
    const int row0 = blockIdx.x * 128;

    for (int i = tid; i < 8192; i += 256) {
        int r = i >> 6;
        int c = (i & 63) * 2;
        float2 xv = make_float2(0.f, 0.f);
        int gr = row0 + r;
        if (gr < NNODES) {
            if (layer) {
                uint32_t raw = *(const uint32_t*)(g_agg + (size_t)gr * DHID + c);
                xv = __bfloat1622float2(*(__nv_bfloat162*)&raw);
                float2 sc = *(const float2*)(g_bnsc + c);
                float2 sh = *(const float2*)(g_bnsh + c);
                xv.x = fmaxf(0.f, xv.x * sc.x + sh.x);
                xv.y = fmaxf(0.f, xv.y * sc.y + sh.y);
            } else {
                xv = *(const float2*)(Xin + (size_t)gr * DHID + c);
            }
        }
        __nv_bfloat162 bv = __floats2bfloat162_rn(xv.x, xv.y);
        *(uint32_t*)(A_sh + r * ST + c) = *(uint32_t*)&bv;
    }
    {
        const uint4* srcw = (const uint4*)(layer ? g_wt1 : g_wt0);
        for (int i = tid; i < 2048; i += 256) {
            int n = i >> 4, kq = i & 15;
            *(uint4*)(B_sh + n * ST + kq * 8) = srcw[i];
        }
    }
    __syncthreads();

    const int wid = tid >> 5, lane = tid & 31;
    const int wm = (wid & 3) * 32;
    const int wn = (wid >> 2) * 64;
    const int g = lane >> 2, q = lane & 3;

    float acc[2][8][4];
#pragma unroll
    for (int mt = 0; mt < 2; mt++)
#pragma unroll
        for (int nt = 0; nt < 8; nt++)
#pragma unroll
            for (int j = 0; j < 4; j++) acc[mt][nt][j] = 0.f;

#pragma unroll
    for (int ks = 0; ks < 8; ks++) {
        int k0 = ks * 16;
        uint32_t af[2][4];
#pragma unroll
        for (int mt = 0; mt < 2; mt++) {
            const __nv_bfloat16* ap = A_sh + (wm + mt * 16 + g) * ST + k0 + q * 2;
            af[mt][0] = *(const uint32_t*)(ap);
            af[mt][1] = *(const uint32_t*)(ap + 8 * ST);
            af[mt][2] = *(const uint32_t*)(ap + 8);
            af[mt][3] = *(const uint32_t*)(ap + 8 * ST + 8);
        }
#pragma unroll
        for (int nt = 0; nt < 8; nt++) {
            const __nv_bfloat16* bp = B_sh + (wn + nt * 8 + g) * ST + k0 + q * 2;
            uint32_t b0 = *(const uint32_t*)(bp);
            uint32_t b1 = *(const uint32_t*)(bp + 8);
#pragma unroll
            for (int mt = 0; mt < 2; mt++)
                mma16816(acc[mt][nt], af[mt][0], af[mt][1], af[mt][2], af[mt][3],
                         b0, b1);
        }
    }

#pragma unroll
    for (int mt = 0; mt < 2; mt++) {
        int r0 = row0 + wm + mt * 16 + g;
        int r1 = r0 + 8;
#pragma unroll
        for (int nt = 0; nt < 8; nt++) {
            int col = wn + nt * 8 + q * 2;
            if (r0 < NNODES) {
                __nv_bfloat162 v = __floats2bfloat162_rn(acc[mt][nt][0],
                                                         acc[mt][nt][1]);
                *(uint32_t*)(g_h + (size_t)r0 * DHID + col) = *(uint32_t*)&v;
            }
            if (r1 < NNODES) {
                __nv_bfloat162 v = __floats2bfloat162_rn(acc[mt][nt][2],
                                                         acc[mt][nt][3]);
                *(uint32_t*)(g_h + (size_t)r1 * DHID + col) = *(uint32_t*)&v;
            }
        }
    }
}

// ---------------- gather conv (R11 proven form: bf16 reads, MLP-4) -----------
__global__ void gather_conv_kernel() {
    int lane = threadIdx.x & 31;
    int warp = (blockIdx.x * blockDim.x + threadIdx.x) >> 5;
    int nw = (gridDim.x * blockDim.x) >> 5;
    float4 s4 = make_float4(0.f, 0.f, 0.f, 0.f);
    float4 q4 = make_float4(0.f, 0.f, 0.f, 0.f);

    for (int n = warp; n < NNODES; n += nw) {
        int beg = __ldg(&g_off[n]);
        int end = __ldg(&g_off[n + 1]);
        float4 acc = make_float4(0.f, 0.f, 0.f, 0.f);
        int e = beg;
        for (; e + 4 <= end; e += 4) {
            int2 p0 = __ldg(g_pe + e);
            int2 p1 = __ldg(g_pe + e + 1);
            int2 p2 = __ldg(g_pe + e + 2);
            int2 p3 = __ldg(g_pe + e + 3);
            uint2 h0 = __ldg((const uint2*)(g_h + (size_t)p0.x * DHID) + lane);
            uint2 h1 = __ldg((const uint2*)(g_h + (size_t)p1.x * DHID) + lane);
            uint2 h2 = __ldg((const uint2*)(g_h + (size_t)p2.x * DHID) + lane);
            uint2 h3 = __ldg((const uint2*)(g_h + (size_t)p3.x * DHID) + lane);
            float w0 = __int_as_float(p0.y), w1 = __int_as_float(p1.y);
            float w2 = __int_as_float(p2.y), w3 = __int_as_float(p3.y);
            float2 a0 = __bfloat1622float2(*(__nv_bfloat162*)&h0.x);
            float2 b0 = __bfloat1622float2(*(__nv_bfloat162*)&h0.y);
            float2 a1 = __bfloat1622float2(*(__nv_bfloat162*)&h1.x);
            float2 b1 = __bfloat1622float2(*(__nv_bfloat162*)&h1.y);
            float2 a2 = __bfloat1622float2(*(__nv_bfloat162*)&h2.x);
            float2 b2 = __bfloat1622float2(*(__nv_bfloat162*)&h2.y);
            float2 a3 = __bfloat1622float2(*(__nv_bfloat162*)&h3.x);
            float2 b3 = __bfloat1622float2(*(__nv_bfloat162*)&h3.y);
            acc.x += a0.x * w0 + a1.x * w1 + a2.x * w2 + a3.x * w3;
            acc.y += a0.y * w0 + a1.y * w1 + a2.y * w2 + a3.y * w3;
            acc.z += b0.x * w0 + b1.x * w1 + b2.x * w2 + b3.x * w3;
            acc.w += b0.y * w0 + b1.y * w1 + b2.y * w2 + b3.y * w3;
        }
        for (; e < end; e++) {
            int2 pe = __ldg(&g_pe[e]);
            float w = __int_as_float(pe.y);
            uint2 hv = __ldg((const uint2*)(g_h + (size_t)pe.x * DHID) + lane);
            float2 f0 = __bfloat1622float2(*(__nv_bfloat162*)&hv.x);
            float2 f1 = __bfloat1622float2(*(__nv_bfloat162*)&hv.y);
            acc.x += f0.x * w; acc.y += f0.y * w;
            acc.z += f1.x * w; acc.w += f1.y * w;
        }
        {
            __nv_bfloat162 lo = __floats2bfloat162_rn(acc.x, acc.y);
            __nv_bfloat162 hi = __floats2bfloat162_rn(acc.z, acc.w);
            uint2 packed = make_uint2(*(uint32_t*)&lo, *(uint32_t*)&hi);
            ((uint2*)(g_agg + (size_t)n * DHID))[lane] = packed;
        }
        s4.x += acc.x; s4.y += acc.y; s4.z += acc.z; s4.w += acc.w;
        q4.x += acc.x * acc.x; q4.y += acc.y * acc.y;
        q4.z += acc.z * acc.z; q4.w += acc.w * acc.w;
    }

    __shared__ float st[2 * DHID];
    if (threadIdx.x < 2 * DHID) st[threadIdx.x] = 0.f;
    __syncthreads();
    int c = lane * 4;
    atomicAdd(&st[c + 0], s4.x); atomicAdd(&st[c + 1], s4.y);
    atomicAdd(&st[c + 2], s4.z); atomicAdd(&st[c + 3], s4.w);
    atomicAdd(&st[DHID + c + 0], q4.x); atomicAdd(&st[DHID + c + 1], q4.y);
    atomicAdd(&st[DHID + c + 2], q4.z); atomicAdd(&st[DHID + c + 3], q4.w);
    __syncthreads();
    if (threadIdx.x < 2 * DHID) atomicAdd(&g_stats[threadIdx.x], st[threadIdx.x]);
}

// ---------------- BN finalize ------------------------------------------------
__global__ void bn_finalize_kernel(const float* __restrict__ gamma,
                                   const float* __restrict__ beta) {
    int c = threadIdx.x;
    const float invN = 1.0f / (float)NNODES;
    float mu = g_stats[c] * invN;
    float var = g_stats[DHID + c] * invN - mu * mu;
    float sc = gamma[c] * rsqrtf(var + 1e-5f);
    g_bnsc[c] = sc;
    g_bnsh[c] = beta[c] - mu * sc;
    g_stats[c] = 0.f;
    g_stats[DHID + c] = 0.f;
}

// ---------------- final: s = sum_n w_out[n] * relu(bn(agg[n])) ---------------
__global__ void node_reduce_kernel() {
    int c = threadIdx.x;
    float sc = g_bnsc[c], sh = g_bnsh[c];
    float s = 0.f;
    for (int n = blockIdx.x; n < NNODES; n += gridDim.x) {
        float v = __bfloat162float(g_agg[(size_t)n * DHID + c]);
        v = fmaxf(0.f, v * sc + sh);
        s += v * g_wout[n];
    }
    atomicAdd(&g_s[c], s);
}

__global__ void final_kernel(const float* __restrict__ W2,
                             const float* __restrict__ b2,
                             float* __restrict__ out) {
    int j = threadIdx.x;
    if (j < DOUT) {
        float acc = 0.f;
        for (int k = 0; k < DHID; k++) acc += g_s[k] * W2[k * DOUT + j];
        out[j] = acc + (float)NNODES * b2[j];
    }
}

// ----------------------------------------------------------------------------
#define GEMM_SMEM (2 * 128 * ST * 2)   // 69632 bytes

extern "C" void kernel_launch(void* const* d_in, const int* in_sizes, int n_in,
                              void* d_out, int out_size) {
    const float* nf  = (const float*)d_in[0];
    const int*   ei  = (const int*)d_in[1];
    const float* ew  = (const float*)d_in[2];
    const float* W0  = (const float*)d_in[3];
    // b0 (d_in[4]) and b1 (d_in[6]) cancel exactly through BatchNorm
    const float* W1  = (const float*)d_in[5];
    const float* W2  = (const float*)d_in[7];
    const float* b2  = (const float*)d_in[8];
    const float* g0  = (const float*)d_in[9];
    const float* be0 = (const float*)d_in[10];
    const float* g1  = (const float*)d_in[11];
    const float* be1 = (const float*)d_in[12];
    const int* src = ei;
    const int* dst = ei + NEDGES;
    float* out = (float*)d_out;

    static int inited = 0;
    if (!inited) {
        cudaFuncSetAttribute(gemm_hmma_kernel,
                             cudaFuncAttributeMaxDynamicSharedMemorySize,
                             GEMM_SMEM);
        inited = 1;
    }

    // CSR build (by dst) + w_out histogram — hierarchical parallel scan
    zero_init_kernel<<<512, 256>>>();
    hist_kernel<<<1024, 256>>>(src, dst, ew);
    scan_sums_kernel<<<SCAN_NB, 256>>>();
    scan_part_kernel<<<1, 128>>>();
    scan_write_kernel<<<SCAN_NB, 256>>>();
    permute_kernel<<<1024, 256>>>(src, dst, ew);
    prep_wt_kernel<<<128, 256>>>(W0, W1);

    // layer 0
    gemm_hmma_kernel<<<NTILES, 256, GEMM_SMEM>>>(nf, 0);
    gather_conv_kernel<<<1184, 256>>>();
    bn_finalize_kernel<<<1, 128>>>(g0, be0);

    // layer 1 (BN0+ReLU fused into A-staging)
    gemm_hmma_kernel<<<NTILES, 256, GEMM_SMEM>>>(nullptr, 1);
    gather_conv_kernel<<<1184, 256>>>();
    bn_finalize_kernel<<<1, 128>>>(g1, be1);

    // final conv collapsed twice: edge sum == w_out-weighted node sum
    node_reduce_kernel<<<2048, 128>>>();
    final_kernel<<<1, 64>>>(W2, b2, out);
}

// round 14
// speedup vs baseline: 2.3647x; 1.6613x over previous
#include <cuda_runtime.h>
#include <cuda_bf16.h>
#include <cuda_fp16.h>
#include <cstdint>

#define NNODES 100000
#define NEDGES 1600000
#define DHID 128
#define DOUT 64
#define NTILES ((NNODES + 127) / 128)   // 782
#define SCAN_BLK 1024
#define SCAN_NB ((NNODES + SCAN_BLK - 1) / SCAN_BLK)   // 98

// ---------------- device scratch (referenced ONLY from device code) ----------
__device__ uint8_t g_h8[(size_t)NNODES * DHID];         // GEMM output, e4m3 fp8
__device__ __nv_bfloat16 g_agg[(size_t)NNODES * DHID];  // gathered aggregate, bf16
__device__ int   g_cnt[SCAN_NB * SCAN_BLK];             // histogram / cursor (padded)
__device__ int   g_off[NNODES + 1];                     // CSR offsets (by dst)
__device__ int   g_part[SCAN_NB];                       // scan block partials
__device__ int2  g_pe[NEDGES + 4];                      // permuted edges {src, w}
__device__ float g_wout[NNODES];                        // per-node outgoing weight
__device__ float g_stats[2 * DHID];
__device__ float g_bnsc[DHID];
__device__ float g_bnsh[DHID];
__device__ float g_s[DHID];
__device__ __nv_bfloat16 g_wt0[DHID * DHID];            // Bt0[n][k] = bf16(W0[k][n])
__device__ __nv_bfloat16 g_wt1[DHID * DHID];            // Bt1[n][k] = bf16(W1[k][n])

// ---------------- fp8 helpers ------------------------------------------------
__device__ __forceinline__ uint16_t f2_to_e4m3x2(float hi, float lo) {
    uint16_t u;
    asm("cvt.rn.satfinite.e4m3x2.f32 %0, %1, %2;" : "=h"(u) : "f"(hi), "f"(lo));
    return u;   // low byte = lo, high byte = hi
}
__device__ __forceinline__ float4 e4m3x4_to_float4(uint32_t v) {
    uint16_t lo = (uint16_t)(v & 0xFFFF);
    uint16_t hi = (uint16_t)(v >> 16);
    uint32_t f01, f23;
    asm("cvt.rn.f16x2.e4m3x2 %0, %1;" : "=r"(f01) : "h"(lo));
    asm("cvt.rn.f16x2.e4m3x2 %0, %1;" : "=r"(f23) : "h"(hi));
    __half2 h01 = *(__half2*)&f01;
    __half2 h23 = *(__half2*)&f23;
    float2 a = __half22float2(h01);
    float2 b = __half22float2(h23);
    return make_float4(a.x, a.y, b.x, b.y);
}

// ---------------- init -------------------------------------------------------
__global__ void zero_init_kernel() {
    int i = blockIdx.x * blockDim.x + threadIdx.x;
    int stride = gridDim.x * blockDim.x;
    for (int j = i; j < SCAN_NB * SCAN_BLK; j += stride) g_cnt[j] = 0;
    for (int j = i; j < NNODES; j += stride) g_wout[j] = 0.f;
    if (i < 2 * DHID) g_stats[i] = 0.f;
    if (i < DHID) g_s[i] = 0.f;
}

// ---------------- CSR build + out-weight histogram ---------------------------
__global__ void hist_kernel(const int* __restrict__ src,
                            const int* __restrict__ dst,
                            const float* __restrict__ ew) {
    int i = blockIdx.x * blockDim.x + threadIdx.x;
    int stride = gridDim.x * blockDim.x;
    for (int e = i; e < NEDGES; e += stride) {
        atomicAdd(&g_cnt[dst[e]], 1);
        atomicAdd(&g_wout[src[e]], ew[e]);
    }
}

__global__ void scan_sums_kernel() {
    __shared__ int sh[256];
    int b = blockIdx.x, t = threadIdx.x;
    const int4* p = (const int4*)(g_cnt + b * SCAN_BLK);
    int4 v = p[t];
    sh[t] = v.x + v.y + v.z + v.w;
    __syncthreads();
    for (int o = 128; o > 0; o >>= 1) {
        if (t < o) sh[t] += sh[t + o];
        __syncthreads();
    }
    if (t == 0) g_part[b] = sh[0];
}

__global__ void scan_part_kernel() {
    __shared__ int sh[128];
    int t = threadIdx.x;
    int v = (t < SCAN_NB) ? g_part[t] : 0;
    sh[t] = v;
    __syncthreads();
    for (int o = 1; o < 128; o <<= 1) {
        int x = (t >= o) ? sh[t - o] : 0;
        __syncthreads();
        sh[t] += x;
        __syncthreads();
    }
    if (t < SCAN_NB) g_part[t] = sh[t] - v;
    if (t == 0) g_off[NNODES] = NEDGES;
}

__global__ void scan_write_kernel() {
    __shared__ int sh[256];
    int b = blockIdx.x, t = threadIdx.x;
    int base = b * SCAN_BLK + t * 4;
    int4 v = ((const int4*)(g_cnt + b * SCAN_BLK))[t];
    int s = v.x + v.y + v.z + v.w;
    sh[t] = s;
    __syncthreads();
    for (int o = 1; o < 256; o <<= 1) {
        int x = (t >= o) ? sh[t - o] : 0;
        __syncthreads();
        sh[t] += x;
        __syncthreads();
    }
    int run = g_part[b] + sh[t] - s;
    int vv[4] = {v.x, v.y, v.z, v.w};
#pragma unroll
    for (int i = 0; i < 4; i++) {
        int idx = base + i;
        if (idx < NNODES) {
            g_off[idx] = run;
            g_cnt[idx] = run;
            run += vv[i];
        }
    }
}

__global__ void permute_kernel(const int* __restrict__ src,
                               const int* __restrict__ dst,
                               const float* __restrict__ ew) {
    int i = blockIdx.x * blockDim.x + threadIdx.x;
    int stride = gridDim.x * blockDim.x;
    for (int e = i; e < NEDGES; e += stride) {
        int d = dst[e];
        int pos = atomicAdd(&g_cnt[d], 1);
        g_pe[pos] = make_int2(src[e], __float_as_int(ew[e]));
    }
}

// ---------------- W prep: Wt[n][k] = bf16(W[k][n]) ---------------------------
__global__ void prep_wt_kernel(const float* __restrict__ W0,
                               const float* __restrict__ W1) {
    int i = blockIdx.x * blockDim.x + threadIdx.x;
    if (i >= 2 * DHID * DHID) return;
    int w = i >> 14;
    int idx = i & 16383;
    int k = idx >> 7, n = idx & 127;
    const float* W = w ? W1 : W0;
    __nv_bfloat16 v = __float2bfloat16(W[k * DHID + n]);
    (w ? g_wt1 : g_wt0)[n * DHID + k] = v;
}

// ---------------- HMMA bf16 GEMM: H = bnrelu?(X) @ W -> e4m3 -----------------
#define ST 136

__device__ __forceinline__ void mma16816(float* c, uint32_t a0, uint32_t a1,
                                         uint32_t a2, uint32_t a3,
                                         uint32_t b0, uint32_t b1) {
    asm volatile(
        "mma.sync.aligned.m16n8k16.row.col.f32.bf16.bf16.f32 "
        "{%0,%1,%2,%3}, {%4,%5,%6,%7}, {%8,%9}, {%0,%1,%2,%3};"
        : "+f"(c[0]), "+f"(c[1]), "+f"(c[2]), "+f"(c[3])
        : "r"(a0), "r"(a1), "r"(a2), "r"(a3), "r"(b0), "r"(b1));
}

__global__ void __launch_bounds__(256)
gemm_hmma_kernel(const float* __restrict__ Xin, int layer) {
    extern __shared__ __nv_bfloat16 sm[];
    __nv_bfloat16* A_sh = sm;              // [128][ST]
    __nv_bfloat16* B_sh = sm + 128 * ST;   // Bt: [n][k], [128][ST]
    const int tid = threadIdx.x;
    const int row0 = blockIdx.x * 128;

    for (int i = tid; i < 8192; i += 256) {
        int r = i >> 6;
        int c = (i & 63) * 2;
        float2 xv = make_float2(0.f, 0.f);
        int gr = row0 + r;
        if (gr < NNODES) {
            if (layer) {
                uint32_t raw = *(const uint32_t*)(g_agg + (size_t)gr * DHID + c);
                xv = __bfloat1622float2(*(__nv_bfloat162*)&raw);
                float2 sc = *(const float2*)(g_bnsc + c);
                float2 sh = *(const float2*)(g_bnsh + c);
                xv.x = fmaxf(0.f, xv.x * sc.x + sh.x);
                xv.y = fmaxf(0.f, xv.y * sc.y + sh.y);
            } else {
                xv = *(const float2*)(Xin + (size_t)gr * DHID + c);
            }
        }
        __nv_bfloat162 bv = __floats2bfloat162_rn(xv.x, xv.y);
        *(uint32_t*)(A_sh + r * ST + c) = *(uint32_t*)&bv;
    }
    {
        const uint4* srcw = (const uint4*)(layer ? g_wt1 : g_wt0);
        for (int i = tid; i < 2048; i += 256) {
            int n = i >> 4, kq = i & 15;
            *(uint4*)(B_sh + n * ST + kq * 8) = srcw[i];
        }
    }
    __syncthreads();

    const int wid = tid >> 5, lane = tid & 31;
    const int wm = (wid & 3) * 32;
    const int wn = (wid >> 2) * 64;
    const int g = lane >> 2, q = lane & 3;

    float acc[2][8][4];
#pragma unroll
    for (int mt = 0; mt < 2; mt++)
#pragma unroll
        for (int nt = 0; nt < 8; nt++)
#pragma unroll
            for (int j = 0; j < 4; j++) acc[mt][nt][j] = 0.f;

#pragma unroll
    for (int ks = 0; ks < 8; ks++) {
        int k0 = ks * 16;
        uint32_t af[2][4];
#pragma unroll
        for (int mt = 0; mt < 2; mt++) {
            const __nv_bfloat16* ap = A_sh + (wm + mt * 16 + g) * ST + k0 + q * 2;
            af[mt][0] = *(const uint32_t*)(ap);
            af[mt][1] = *(const uint32_t*)(ap + 8 * ST);
            af[mt][2] = *(const uint32_t*)(ap + 8);
            af[mt][3] = *(const uint32_t*)(ap + 8 * ST + 8);
        }
#pragma unroll
        for (int nt = 0; nt < 8; nt++) {
            const __nv_bfloat16* bp = B_sh + (wn + nt * 8 + g) * ST + k0 + q * 2;
            uint32_t b0 = *(const uint32_t*)(bp);
            uint32_t b1 = *(const uint32_t*)(bp + 8);
#pragma unroll
            for (int mt = 0; mt < 2; mt++)
                mma16816(acc[mt][nt], af[mt][0], af[mt][1], af[mt][2], af[mt][3],
                         b0, b1);
        }
    }

    // epilogue: fp32 -> e4m3 (2-byte stores)
#pragma unroll
    for (int mt = 0; mt < 2; mt++) {
        int r0 = row0 + wm + mt * 16 + g;
        int r1 = r0 + 8;
#pragma unroll
        for (int nt = 0; nt < 8; nt++) {
            int col = wn + nt * 8 + q * 2;
            if (r0 < NNODES) {
                uint16_t u = f2_to_e4m3x2(acc[mt][nt][1], acc[mt][nt][0]);
                *(uint16_t*)(g_h8 + (size_t)r0 * DHID + col) = u;
            }
            if (r1 < NNODES) {
                uint16_t u = f2_to_e4m3x2(acc[mt][nt][3], acc[mt][nt][2]);
                *(uint16_t*)(g_h8 + (size_t)r1 * DHID + col) = u;
            }
        }
    }
}

// ---------------- gather conv (fp8 reads, MLP-4 inner loop) ------------------
// One warp per node; lane loads uint32 = 4 e4m3 cols; fp32 accumulation;
// bf16 agg store; fused BN stats.
__global__ void gather_conv_kernel() {
    int lane = threadIdx.x & 31;
    int warp = (blockIdx.x * blockDim.x + threadIdx.x) >> 5;
    int nw = (gridDim.x * blockDim.x) >> 5;
    float4 s4 = make_float4(0.f, 0.f, 0.f, 0.f);
    float4 q4 = make_float4(0.f, 0.f, 0.f, 0.f);

    for (int n = warp; n < NNODES; n += nw) {
        int beg = __ldg(&g_off[n]);
        int end = __ldg(&g_off[n + 1]);
        float4 acc = make_float4(0.f, 0.f, 0.f, 0.f);
        int e = beg;
        for (; e + 4 <= end; e += 4) {
            int2 p0 = __ldg(g_pe + e);
            int2 p1 = __ldg(g_pe + e + 1);
            int2 p2 = __ldg(g_pe + e + 2);
            int2 p3 = __ldg(g_pe + e + 3);
            uint32_t h0 = __ldg((const uint32_t*)(g_h8 + (size_t)p0.x * DHID) + lane);
            uint32_t h1 = __ldg((const uint32_t*)(g_h8 + (size_t)p1.x * DHID) + lane);
            uint32_t h2 = __ldg((const uint32_t*)(g_h8 + (size_t)p2.x * DHID) + lane);
            uint32_t h3 = __ldg((const uint32_t*)(g_h8 + (size_t)p3.x * DHID) + lane);
            float w0 = __int_as_float(p0.y), w1 = __int_as_float(p1.y);
            float w2 = __int_as_float(p2.y), w3 = __int_as_float(p3.y);
            float4 f0 = e4m3x4_to_float4(h0);
            float4 f1 = e4m3x4_to_float4(h1);
            float4 f2 = e4m3x4_to_float4(h2);
            float4 f3 = e4m3x4_to_float4(h3);
            acc.x += f0.x * w0 + f1.x * w1 + f2.x * w2 + f3.x * w3;
            acc.y += f0.y * w0 + f1.y * w1 + f2.y * w2 + f3.y * w3;
            acc.z += f0.z * w0 + f1.z * w1 + f2.z * w2 + f3.z * w3;
            acc.w += f0.w * w0 + f1.w * w1 + f2.w * w2 + f3.w * w3;
        }
        for (; e < end; e++) {
            int2 pe = __ldg(&g_pe[e]);
            float w = __int_as_float(pe.y);
            uint32_t hv = __ldg((const uint32_t*)(g_h8 + (size_t)pe.x * DHID) + lane);
            float4 f = e4m3x4_to_float4(hv);
            acc.x += f.x * w; acc.y += f.y * w;
            acc.z += f.z * w; acc.w += f.w * w;
        }
        {
            __nv_bfloat162 lo = __floats2bfloat162_rn(acc.x, acc.y);
            __nv_bfloat162 hi = __floats2bfloat162_rn(acc.z, acc.w);
            uint2 packed = make_uint2(*(uint32_t*)&lo, *(uint32_t*)&hi);
            ((uint2*)(g_agg + (size_t)n * DHID))[lane] = packed;
        }
        s4.x += acc.x; s4.y += acc.y; s4.z += acc.z; s4.w += acc.w;
        q4.x += acc.x * acc.x; q4.y += acc.y * acc.y;
        q4.z += acc.z * acc.z; q4.w += acc.w * acc.w;
    }

    __shared__ float st[2 * DHID];
    if (threadIdx.x < 2 * DHID) st[threadIdx.x] = 0.f;
    __syncthreads();
    int c = lane * 4;
    atomicAdd(&st[c + 0], s4.x); atomicAdd(&st[c + 1], s4.y);
    atomicAdd(&st[c + 2], s4.z); atomicAdd(&st[c + 3], s4.w);
    atomicAdd(&st[DHID + c + 0], q4.x); atomicAdd(&st[DHID + c + 1], q4.y);
    atomicAdd(&st[DHID + c + 2], q4.z); atomicAdd(&st[DHID + c + 3], q4.w);
    __syncthreads();
    if (threadIdx.x < 2 * DHID) atomicAdd(&g_stats[threadIdx.x], st[threadIdx.x]);
}

// ---------------- BN finalize ------------------------------------------------
__global__ void bn_finalize_kernel(const float* __restrict__ gamma,
                                   const float* __restrict__ beta) {
    int c = threadIdx.x;
    const float invN = 1.0f / (float)NNODES;
    float mu = g_stats[c] * invN;
    float var = g_stats[DHID + c] * invN - mu * mu;
    float sc = gamma[c] * rsqrtf(var + 1e-5f);
    g_bnsc[c] = sc;
    g_bnsh[c] = beta[c] - mu * sc;
    g_stats[c] = 0.f;
    g_stats[DHID + c] = 0.f;
}

// ---------------- final: s = sum_n w_out[n] * relu(bn(agg[n])) ---------------
__global__ void node_reduce_kernel() {
    int c = threadIdx.x;
    float sc = g_bnsc[c], sh = g_bnsh[c];
    float s = 0.f;
    for (int n = blockIdx.x; n < NNODES; n += gridDim.x) {
        float v = __bfloat162float(g_agg[(size_t)n * DHID + c]);
        v = fmaxf(0.f, v * sc + sh);
        s += v * g_wout[n];
    }
    atomicAdd(&g_s[c], s);
}

__global__ void final_kernel(const float* __restrict__ W2,
                             const float* __restrict__ b2,
                             float* __restrict__ out) {
    int j = threadIdx.x;
    if (j < DOUT) {
        float acc = 0.f;
        for (int k = 0; k < DHID; k++) acc += g_s[k] * W2[k * DOUT + j];
        out[j] = acc + (float)NNODES * b2[j];
    }
}

// ----------------------------------------------------------------------------
#define GEMM_SMEM (2 * 128 * ST * 2)   // 69632 bytes

extern "C" void kernel_launch(void* const* d_in, const int* in_sizes, int n_in,
                              void* d_out, int out_size) {
    const float* nf  = (const float*)d_in[0];
    const int*   ei  = (const int*)d_in[1];
    const float* ew  = (const float*)d_in[2];
    const float* W0  = (const float*)d_in[3];
    // b0 (d_in[4]) and b1 (d_in[6]) cancel exactly through BatchNorm
    const float* W1  = (const float*)d_in[5];
    const float* W2  = (const float*)d_in[7];
    const float* b2  = (const float*)d_in[8];
    const float* g0  = (const float*)d_in[9];
    const float* be0 = (const float*)d_in[10];
    const float* g1  = (const float*)d_in[11];
    const float* be1 = (const float*)d_in[12];
    const int* src = ei;
    const int* dst = ei + NEDGES;
    float* out = (float*)d_out;

    static int inited = 0;
    if (!inited) {
        cudaFuncSetAttribute(gemm_hmma_kernel,
                             cudaFuncAttributeMaxDynamicSharedMemorySize,
                             GEMM_SMEM);
        inited = 1;
    }

    // CSR build (by dst) + w_out histogram — hierarchical parallel scan
    zero_init_kernel<<<512, 256>>>();
    hist_kernel<<<1024, 256>>>(src, dst, ew);
    scan_sums_kernel<<<SCAN_NB, 256>>>();
    scan_part_kernel<<<1, 128>>>();
    scan_write_kernel<<<SCAN_NB, 256>>>();
    permute_kernel<<<1024, 256>>>(src, dst, ew);
    prep_wt_kernel<<<128, 256>>>(W0, W1);

    // layer 0
    gemm_hmma_kernel<<<NTILES, 256, GEMM_SMEM>>>(nf, 0);
    gather_conv_kernel<<<1184, 256>>>();
    bn_finalize_kernel<<<1, 128>>>(g0, be0);

    // layer 1 (BN0+ReLU fused into A-staging)
    gemm_hmma_kernel<<<NTILES, 256, GEMM_SMEM>>>(nullptr, 1);
    gather_conv_kernel<<<1184, 256>>>();
    bn_finalize_kernel<<<1, 128>>>(g1, be1);

    // final conv collapsed twice: edge sum == w_out-weighted node sum
    node_reduce_kernel<<<2048, 128>>>();
    final_kernel<<<1, 64>>>(W2, b2, out);
}